// round 7
// baseline (speedup 1.0000x reference)
#include <cuda_runtime.h>

#define DEGREE 20

// Rescaled Clenshaw evaluation of sum_k W_k * P_k(x), then * (1 - x^2),
// two elements per instruction via packed fma.rn.f32x2 (PTX-only on sm_100a;
// ptxas never auto-fuses scalar fmaf pairs).
//
//   d_k = cp_k + x d_{k+1} + g_k d_{k+2},  S = d_0
//   cp_k = W_k * C(2k,k)/2^k,  g_k = -(k+1)^2/((2k+1)(2k+3))
//
// R1: 32-reg cap spilled cp[] (LDL in loop).
// R3: occ==issue -> latency-bound, MLP=1 exposed DRAM latency.
// R4: depth-1 pipeline -> 18.6us, issue 69.5%; instruction-count bound
//     (63 fma-pipe cyc / warp-elem floor ~= 14us for the scalar form).
// R5: f32x2 packs 2 FMAs/instr at full pipe rate -> 42 cyc / warp-elem and
//     half the issue slots; depth-2 prefetch covers DRAM latency at the
//     reduced occupancy (128-reg budget, 2 blocks/SM).
// R5/R6 reruns: container-level infra failures (same error previously hit
//     the scalar kernel in R2, which then ran fine) — source unchanged.

typedef unsigned long long ull;

__device__ __forceinline__ ull pack2(float a, float b) {
    ull r;
    asm("mov.b64 %0, {%1, %2};" : "=l"(r) : "f"(a), "f"(b));
    return r;
}
__device__ __forceinline__ float lo2(ull p) {
    float a, b;
    asm("mov.b64 {%0, %1}, %2;" : "=f"(a), "=f"(b) : "l"(p));
    return a;
}
__device__ __forceinline__ ull fma2(ull a, ull b, ull c) {
    ull r;
    asm("fma.rn.f32x2 %0, %1, %2, %3;" : "=l"(r) : "l"(a), "l"(b), "l"(c));
    return r;
}
__device__ __forceinline__ ull mul2(ull a, ull b) {
    ull r;
    asm("mul.rn.f32x2 %0, %1, %2;" : "=l"(r) : "l"(a), "l"(b));
    return r;
}

// Packed Clenshaw on two x values; returns (1-x^2)*sum for both lanes.
__device__ __forceinline__ ull clenshaw2(ull x2, const ull* __restrict__ cp2,
                                         const ull* __restrict__ g2, ull ones) {
    ull d1 = 0ull, d2 = 0ull;
#pragma unroll
    for (int k = DEGREE; k >= 0; --k) {
        ull u = fma2(g2[k], d2, cp2[k]);
        ull d0 = fma2(x2, d1, u);
        d2 = d1;
        d1 = d0;
    }
    ull nx2 = x2 ^ 0x8000000080000000ull;      // negate both lanes (LOP3)
    ull bc = fma2(nx2, x2, ones);              // 1 - x^2
    return mul2(d1, bc);
}

__global__ __launch_bounds__(256, 2) void legendre_kernel(
    const float* __restrict__ x, const float* __restrict__ W,
    float* __restrict__ out, int n)
{
    // Prologue: packed coefficients (both lanes identical), ~90 instrs,
    // amortized over ~26 iterations/thread.
    ull cp2[DEGREE + 1];
    ull g2[DEGREE + 1];
    {
        float M = 1.0f;
        float c0 = __ldg(&W[0]);
        cp2[0] = pack2(c0, c0);
#pragma unroll
        for (int k = 1; k <= DEGREE; ++k) {
            M *= (float)(2 * k - 1) / (float)k;   // folds to immediate
            float c = __ldg(&W[k]) * M;
            cp2[k] = pack2(c, c);
        }
#pragma unroll
        for (int k = 0; k <= DEGREE; ++k) {
            float g = -(float)((k + 1) * (k + 1)) / (float)((2 * k + 1) * (2 * k + 3));
            g2[k] = pack2(g, g);                  // compile-time lanes
        }
    }
    const ull ones = pack2(1.0f, 1.0f);

    const int tid = blockIdx.x * blockDim.x + threadIdx.x;
    const int stride = gridDim.x * blockDim.x;
    const int n4 = n >> 2;   // count of float4 / ulonglong2 elements

    const ulonglong2* __restrict__ xp = (const ulonglong2*)x;
    ulonglong2* __restrict__ op = (ulonglong2*)out;

    // Depth-2 software pipeline: two LDG.128 in flight ahead of compute
    // (~670 cycles of packed Clenshaw per iteration covers DRAM latency).
    int i = tid;
    if (i < n4) {
        ulonglong2 a = xp[i];
        int i1 = i + stride;
        if (i1 < n4) {
            ulonglong2 b = xp[i1];
            while (i1 + stride < n4) {
                ulonglong2 c = xp[i1 + stride];
                ulonglong2 r;
                r.x = clenshaw2(a.x, cp2, g2, ones);
                r.y = clenshaw2(a.y, cp2, g2, ones);
                op[i] = r;
                a = b; b = c;
                i = i1; i1 += stride;
            }
            ulonglong2 r;
            r.x = clenshaw2(a.x, cp2, g2, ones);
            r.y = clenshaw2(a.y, cp2, g2, ones);
            op[i] = r;
            r.x = clenshaw2(b.x, cp2, g2, ones);
            r.y = clenshaw2(b.y, cp2, g2, ones);
            op[i1] = r;
        } else {
            ulonglong2 r;
            r.x = clenshaw2(a.x, cp2, g2, ones);
            r.y = clenshaw2(a.y, cp2, g2, ones);
            op[i] = r;
        }
    }

    // Scalar tail (n % 4 != 0) — not hit for n = 8,000,000 but kept correct.
    for (int j = (n4 << 2) + tid; j < n; j += stride) {
        float xx = x[j];
        out[j] = lo2(clenshaw2(pack2(xx, xx), cp2, g2, ones));
    }
}

extern "C" void kernel_launch(void* const* d_in, const int* in_sizes, int n_in,
                              void* d_out, int out_size) {
    // Identify W by its element count (DEGREE+1); x is the big array.
    const float* x = (const float*)d_in[0];
    const float* W = (const float*)d_in[1];
    if (n_in >= 2 && in_sizes[0] == DEGREE + 1 && in_sizes[1] != DEGREE + 1) {
        x = (const float*)d_in[1];
        W = (const float*)d_in[0];
    }
    float* out = (float*)d_out;
    int n = out_size;

    // One full wave at 2 blocks/SM (128-reg budget) on 148 SMs;
    // ~26 float4 iterations/thread amortizes the coefficient prologue.
    legendre_kernel<<<296, 256>>>(x, W, out, n);
}

// round 8
// speedup vs baseline: 1.0260x; 1.0260x over previous
#include <cuda_runtime.h>

#define DEGREE 20

// Rescaled Clenshaw evaluation of sum_k W_k * P_k(x), then * (1 - x^2),
// two elements per instruction via packed fma.rn.f32x2 (PTX-only on sm_100a;
// ptxas never auto-fuses scalar fmaf pairs).
//
//   d_k = cp_k + x d_{k+1} + g_k d_{k+2},  S = d_0
//   cp_k = W_k * C(2k,k)/2^k,  g_k = -(k+1)^2/((2k+1)(2k+3))
//
// R1: 32-reg cap spilled cp[] (LDL in loop).
// R3: occ==issue -> latency-bound, MLP=1 exposed DRAM latency.
// R4: depth-1 pipeline -> 18.6us, issue 69.5%; scalar form is
//     instruction-count bound (~63 fma-pipe cyc / warp-elem).
// R7: f32x2 halved pipe demand (fma-busy ~9.6us == packed floor) but
//     grid=296 @ regs=78 capped residency at 2 blocks/SM (occ 20.1%,
//     issue 39.8%) -> pipe half idle, dur neutral at 18.6us.
// R8: occupancy fix only — launch_bounds(256,3) + grid 444 (= 3x148, one
//     full wave at 3 blocks/SM). 6 warps/SMSP x 2 chains each covers the
//     FFMA2 latency chain; compute body unchanged.

typedef unsigned long long ull;

__device__ __forceinline__ ull pack2(float a, float b) {
    ull r;
    asm("mov.b64 %0, {%1, %2};" : "=l"(r) : "f"(a), "f"(b));
    return r;
}
__device__ __forceinline__ float lo2(ull p) {
    float a, b;
    asm("mov.b64 {%0, %1}, %2;" : "=f"(a), "=f"(b) : "l"(p));
    return a;
}
__device__ __forceinline__ ull fma2(ull a, ull b, ull c) {
    ull r;
    asm("fma.rn.f32x2 %0, %1, %2, %3;" : "=l"(r) : "l"(a), "l"(b), "l"(c));
    return r;
}
__device__ __forceinline__ ull mul2(ull a, ull b) {
    ull r;
    asm("mul.rn.f32x2 %0, %1, %2;" : "=l"(r) : "l"(a), "l"(b));
    return r;
}

// Packed Clenshaw on two x values; returns (1-x^2)*sum for both lanes.
__device__ __forceinline__ ull clenshaw2(ull x2, const ull* __restrict__ cp2,
                                         const ull* __restrict__ g2, ull ones) {
    ull d1 = 0ull, d2 = 0ull;
#pragma unroll
    for (int k = DEGREE; k >= 0; --k) {
        ull u = fma2(g2[k], d2, cp2[k]);
        ull d0 = fma2(x2, d1, u);
        d2 = d1;
        d1 = d0;
    }
    ull nx2 = x2 ^ 0x8000000080000000ull;      // negate both lanes (LOP3)
    ull bc = fma2(nx2, x2, ones);              // 1 - x^2
    return mul2(d1, bc);
}

__global__ __launch_bounds__(256, 3) void legendre_kernel(
    const float* __restrict__ x, const float* __restrict__ W,
    float* __restrict__ out, int n)
{
    // Prologue: packed coefficients (both lanes identical), ~90 instrs,
    // amortized over ~17 iterations/thread.
    ull cp2[DEGREE + 1];
    ull g2[DEGREE + 1];
    {
        float M = 1.0f;
        float c0 = __ldg(&W[0]);
        cp2[0] = pack2(c0, c0);
#pragma unroll
        for (int k = 1; k <= DEGREE; ++k) {
            M *= (float)(2 * k - 1) / (float)k;   // folds to immediate
            float c = __ldg(&W[k]) * M;
            cp2[k] = pack2(c, c);
        }
#pragma unroll
        for (int k = 0; k <= DEGREE; ++k) {
            float g = -(float)((k + 1) * (k + 1)) / (float)((2 * k + 1) * (2 * k + 3));
            g2[k] = pack2(g, g);                  // compile-time lanes
        }
    }
    const ull ones = pack2(1.0f, 1.0f);

    const int tid = blockIdx.x * blockDim.x + threadIdx.x;
    const int stride = gridDim.x * blockDim.x;
    const int n4 = n >> 2;   // count of float4 / ulonglong2 elements

    const ulonglong2* __restrict__ xp = (const ulonglong2*)x;
    ulonglong2* __restrict__ op = (ulonglong2*)out;

    // Depth-2 software pipeline: two LDG.128 in flight ahead of compute.
    int i = tid;
    if (i < n4) {
        ulonglong2 a = xp[i];
        int i1 = i + stride;
        if (i1 < n4) {
            ulonglong2 b = xp[i1];
            while (i1 + stride < n4) {
                ulonglong2 c = xp[i1 + stride];
                ulonglong2 r;
                r.x = clenshaw2(a.x, cp2, g2, ones);
                r.y = clenshaw2(a.y, cp2, g2, ones);
                op[i] = r;
                a = b; b = c;
                i = i1; i1 += stride;
            }
            ulonglong2 r;
            r.x = clenshaw2(a.x, cp2, g2, ones);
            r.y = clenshaw2(a.y, cp2, g2, ones);
            op[i] = r;
            r.x = clenshaw2(b.x, cp2, g2, ones);
            r.y = clenshaw2(b.y, cp2, g2, ones);
            op[i1] = r;
        } else {
            ulonglong2 r;
            r.x = clenshaw2(a.x, cp2, g2, ones);
            r.y = clenshaw2(a.y, cp2, g2, ones);
            op[i] = r;
        }
    }

    // Scalar tail (n % 4 != 0) — not hit for n = 8,000,000 but kept correct.
    for (int j = (n4 << 2) + tid; j < n; j += stride) {
        float xx = x[j];
        out[j] = lo2(clenshaw2(pack2(xx, xx), cp2, g2, ones));
    }
}

extern "C" void kernel_launch(void* const* d_in, const int* in_sizes, int n_in,
                              void* d_out, int out_size) {
    // Identify W by its element count (DEGREE+1); x is the big array.
    const float* x = (const float*)d_in[0];
    const float* W = (const float*)d_in[1];
    if (n_in >= 2 && in_sizes[0] == DEGREE + 1 && in_sizes[1] != DEGREE + 1) {
        x = (const float*)d_in[1];
        W = (const float*)d_in[0];
    }
    float* out = (float*)d_out;
    int n = out_size;

    // 444 = exactly 3 resident blocks/SM on 148 SMs (one full wave at the
    // 85-reg budget; kernel uses 78). ~17 iters/thread amortizes prologue.
    legendre_kernel<<<444, 256>>>(x, W, out, n);
}